// round 12
// baseline (speedup 1.0000x reference)
#include <cuda_runtime.h>
#include <cuda_bf16.h>
#include <cstdint>

#define T_SEQ   80
#define NCLS    80
#define HID     256
#define EMB     8
#define BATCH   8192
#define GATES   1024
#define M_CTA   64
#define NCTA    (BATCH / M_CTA)
#define NTHREADS 512

#define KT1     18                  // layer1 K = 288 (bias+pad+x+h1+zero-pad), %3==0
#define KT2     33                  // layer2 K = 528, %3==0
#define A_STRIDE   536              // bf16 elems/row; 1072B % 128 = 48 -> conflict-free ldmatrix
#define A_STRIDE_B (A_STRIDE * 2)
#define C_STRIDE   264

#define SM_A        0
#define SM_A_BYTES  (M_CTA * A_STRIDE_B)
#define SM_C1       SM_A_BYTES
#define SM_CBYTES   (M_CTA * C_STRIDE * 4)
#define SM_C2       (SM_C1 + SM_CBYTES)
#define SM_EMB      (SM_C2 + SM_CBYTES)
#define SM_LOGITS   (SM_EMB + NCLS * EMB * 4)
#define SM_TOTAL    (SM_LOGITS + M_CTA * NCLS * 4)   // 226816 bytes

// Packed weights for M16/N64 passes, hidden-16-block major:
//   uint2 flat = ((hp*KT + kt)*32 + lane)*8 + (gi*2 + nh)
//   hp in [0,16) = hidden-col block of 16, gi = gate, nh = n8-half of the 16 cols.
//   n = gi*256 + hp*16 + nh*8 + (lane>>2); k rows k0,k0+1,k0+8,k0+9, k0 = kt*16+(lane&3)*2.
// Per (kt,lane): 8 uint2 = 4 uint4 contiguous -> 4x LDG.128 per k-tile.
#define N1PK (32 * KT1 * 128)
#define N2PK (32 * KT2 * 128)
__device__ uint4 g_W1p[32 * KT1 * 64];
__device__ uint4 g_W2p[32 * KT2 * 64];

// Extended row r: r==0 -> bias[n]; r<woff or r>=rmax -> 0; else W[r-woff][n]
__global__ void pack_all(const float* __restrict__ W1, const float* __restrict__ b1,
                         const float* __restrict__ W2, const float* __restrict__ b2)
{
    int idx = blockIdx.x * blockDim.x + threadIdx.x;
    if (idx >= N1PK + N2PK) return;
    const float *W, *b; uint2* out; int KT, woff, rmax, rem;
    if (idx < N1PK) { W = W1; b = b1; out = (uint2*)g_W1p; KT = KT1; woff = 8;  rmax = 272; rem = idx; }
    else            { W = W2; b = b2; out = (uint2*)g_W2p; KT = KT2; woff = 16; rmax = 528; rem = idx - N1PK; }
    int frag = rem & 7;                  // gi*2 + nh
    int gi   = frag >> 1;
    int nh   = frag & 1;
    int lane = (rem >> 3) & 31;
    int t    = rem >> 8;
    int kt   = t % KT;
    int hp   = t / KT;                   // [0,16)
    int th = lane & 3, g = lane >> 2;
    int n  = gi * 256 + hp * 16 + nh * 8 + g;
    int k0 = kt * 16 + th * 2;
    float v[4];
#pragma unroll
    for (int i = 0; i < 4; i++) {
        int r = k0 + ((i >> 1) * 8) + (i & 1);   // k0,k0+1,k0+8,k0+9
        float val;
        if (r == 0)                     val = b[n];
        else if (r < woff || r >= rmax) val = 0.f;
        else                            val = W[(size_t)(r - woff) * GATES + n];
        v[i] = val;
    }
    __nv_bfloat162 p0 = __floats2bfloat162_rn(v[0], v[1]);
    __nv_bfloat162 p1 = __floats2bfloat162_rn(v[2], v[3]);
    uint2 o;
    o.x = *reinterpret_cast<uint32_t*>(&p0);
    o.y = *reinterpret_cast<uint32_t*>(&p1);
    out[rem] = o;
}

__device__ __forceinline__ float fast_tanh(float x) {
    float y; asm("tanh.approx.f32 %0, %1;" : "=f"(y) : "f"(x)); return y;
}
__device__ __forceinline__ float fast_sigmoid(float x) {
    return fmaf(fast_tanh(0.5f * x), 0.5f, 0.5f);
}
__device__ __forceinline__ void ldsm4(uint32_t a[4], uint32_t addr) {
    asm volatile("ldmatrix.sync.aligned.m8n8.x4.shared.b16 {%0,%1,%2,%3}, [%4];\n"
                 : "=r"(a[0]), "=r"(a[1]), "=r"(a[2]), "=r"(a[3]) : "r"(addr));
}
__device__ __forceinline__ void mma_bf16(float c[4], const uint32_t a[4], uint32_t b0, uint32_t b1) {
    asm volatile("mma.sync.aligned.m16n8k16.row.col.f32.bf16.bf16.f32 "
                 "{%0,%1,%2,%3}, {%4,%5,%6,%7}, {%8,%9}, {%0,%1,%2,%3};\n"
                 : "+f"(c[0]), "+f"(c[1]), "+f"(c[2]), "+f"(c[3])
                 : "r"(a[0]), "r"(a[1]), "r"(a[2]), "r"(a[3]), "r"(b0), "r"(b1));
}

// 8 mmas of one k-tile: 4 gates x 2 n8-halves, single M=16 A fragment.
__device__ __forceinline__ void do8(float (&acc)[4][2][4], const uint32_t (&af)[4],
                                    const uint4 (&S)[4])
{
#pragma unroll
    for (int gi = 0; gi < 4; gi++) {
        mma_bf16(acc[gi][0], af, S[gi].x, S[gi].y);
        mma_bf16(acc[gi][1], af, S[gi].z, S[gi].w);
    }
}

// One LSTM layer. 16 warps = 4 wm (16 rows each) x 4 wn. Each warp does 4 passes;
// pass p covers hidden cols [ (wn*4+p)*16, +16 ) x all 4 gates (N=64) from ONE
// ldsm4 per k-tile. B and A both in 3-set rotating buffers (no register shifts).
template<int KT>
__device__ __forceinline__ void lstm_layer(
    uint32_t sbase, const uint4* __restrict__ Wp,
    float* __restrict__ cbuf, uint32_t (&hnew)[4][2][2],
    int wm, int wn, int lane)
{
    static_assert(KT % 3 == 0, "KT must be divisible by 3");
    const int th = lane & 3, g = lane >> 2;
    const uint32_t a_base = sbase +
        (uint32_t)((wm * 16 + (lane & 15)) * A_STRIDE_B + ((lane >> 4) << 4));

#pragma unroll
    for (int p = 0; p < 4; p++) {
        const int hp = wn * 4 + p;
        float acc[4][2][4];
#pragma unroll
        for (int gi = 0; gi < 4; gi++)
#pragma unroll
            for (int nh = 0; nh < 2; nh++)
#pragma unroll
                for (int i = 0; i < 4; i++) acc[gi][nh][i] = 0.f;

        const uint4* bb = Wp + ((size_t)(hp * KT) * 32 + lane) * 4;
        uint4 S0[4], S1[4], S2[4];
#pragma unroll
        for (int j = 0; j < 4; j++) {
            S0[j] = __ldg(bb + j);
            S1[j] = __ldg(bb + 128 + j);
            S2[j] = __ldg(bb + 256 + j);
        }

        uint32_t af0[4], af1[4], af2[4];
        uint32_t am = a_base;
        ldsm4(af0, am); ldsm4(af1, am + 32); ldsm4(af2, am + 64);

#pragma unroll 1
        for (int kt = 0; kt < KT; kt += 3) {
            // substep 0: consume set 0, refill for kt+3
            do8(acc, af0, S0);
            if (kt + 3 < KT) {
                ldsm4(af0, am + 96);
#pragma unroll
                for (int j = 0; j < 4; j++) S0[j] = __ldg(bb + 384 + j);
            }
            // substep 1: consume set 1, refill for kt+4
            do8(acc, af1, S1);
            if (kt + 4 < KT) {
                ldsm4(af1, am + 128);
#pragma unroll
                for (int j = 0; j < 4; j++) S1[j] = __ldg(bb + 512 + j);
            }
            // substep 2: consume set 2, refill for kt+5
            do8(acc, af2, S2);
            if (kt + 5 < KT) {
                ldsm4(af2, am + 160);
#pragma unroll
                for (int j = 0; j < 4; j++) S2[j] = __ldg(bb + 640 + j);
            }
            bb += 384; am += 96;
        }

        // elementwise: thread owns rows {wm*16+g, +8}, cols hp*16 + nh*8 + th*2 (+1)
#pragma unroll
        for (int nh = 0; nh < 2; nh++) {
#pragma unroll
            for (int rb = 0; rb < 2; rb++) {
                const int r = wm * 16 + g + rb * 8;
                float* cc = cbuf + r * C_STRIDE + hp * 16 + nh * 8 + th * 2;
                float2 cold = *reinterpret_cast<float2*>(cc);
                float co[2] = { cold.x, cold.y };
                float nc[2], hv[2];
#pragma unroll
                for (int q = 0; q < 2; q++) {
                    const int ci = rb * 2 + q;
                    nc[q] = co[q] * fast_sigmoid(acc[2][nh][ci] + 1.0f)
                          + fast_sigmoid(acc[0][nh][ci]) * fast_tanh(acc[1][nh][ci]);
                    hv[q] = fast_tanh(nc[q]) * fast_sigmoid(acc[3][nh][ci]);
                }
                *reinterpret_cast<float2*>(cc) = make_float2(nc[0], nc[1]);
                __nv_bfloat162 hp2 = __floats2bfloat162_rn(hv[0], hv[1]);
                hnew[p][nh][rb] = *reinterpret_cast<uint32_t*>(&hp2);
            }
        }
    }
}

__device__ __forceinline__ void store_h(char* smem, const uint32_t (&hnew)[4][2][2],
                                        int hoff, int wm, int wn, int lane)
{
    const int th = lane & 3, g = lane >> 2;
#pragma unroll
    for (int p = 0; p < 4; p++) {
        const int hp = wn * 4 + p;
#pragma unroll
        for (int nh = 0; nh < 2; nh++)
#pragma unroll
            for (int rb = 0; rb < 2; rb++) {
                const int r = wm * 16 + g + rb * 8;
                const int col = hoff + hp * 16 + nh * 8 + th * 2;
                *reinterpret_cast<uint32_t*>(smem + r * A_STRIDE_B + col * 2) = hnew[p][nh][rb];
            }
    }
}

__device__ __forceinline__ void write_x(char* smem, float* embs,
                                        const int* __restrict__ features,
                                        int rowbase, int t, int tid)
{
    if (tid < M_CTA) {
        int f = features[(rowbase + tid) * T_SEQ + t];
        const float* e = embs + f * EMB;
        uint32_t* dst = reinterpret_cast<uint32_t*>(smem + tid * A_STRIDE_B + 16);
#pragma unroll
        for (int i = 0; i < 4; i++) {
            __nv_bfloat162 p = __floats2bfloat162_rn(e[2 * i], e[2 * i + 1]);
            dst[i] = *reinterpret_cast<uint32_t*>(&p);
        }
    }
}

__global__ void __launch_bounds__(NTHREADS, 1) lstm_kernel(
    const int* __restrict__ features, const int* __restrict__ labels,
    const float* __restrict__ embedding,
    const float* __restrict__ Wd, const float* __restrict__ bd,
    float* __restrict__ out)
{
    extern __shared__ char smem[];
    const int tid = threadIdx.x;
    const int w = tid >> 5, lane = tid & 31;
    const int wm = w >> 2, wn = w & 3;
    const int rowbase = blockIdx.x * M_CTA;

    float* c1   = (float*)(smem + SM_C1);
    float* c2   = (float*)(smem + SM_C2);
    float* embs = (float*)(smem + SM_EMB);

    for (int i = tid; i < SM_TOTAL / 4; i += NTHREADS)
        ((uint32_t*)smem)[i] = 0u;
    __syncthreads();
    if (tid < M_CTA)
        *reinterpret_cast<__nv_bfloat16*>(smem + tid * A_STRIDE_B) = __float2bfloat16(1.0f);
    for (int i = tid; i < NCLS * EMB; i += NTHREADS) embs[i] = embedding[i];
    __syncthreads();
    write_x(smem, embs, features, rowbase, 0, tid);
    __syncthreads();

    const uint32_t sbase = (uint32_t)__cvta_generic_to_shared(smem);
    uint32_t hnew[4][2][2];

    for (int t = 0; t < T_SEQ; t++) {
        lstm_layer<KT1>(sbase, g_W1p, c1, hnew, wm, wn, lane);
        __syncthreads();
        store_h(smem, hnew, 16, wm, wn, lane);                  // h1 -> cols 16..271
        if (t + 1 < T_SEQ) write_x(smem, embs, features, rowbase, t + 1, tid);
        __syncthreads();   // layer2 reads x-cols against ZERO weight rows: values don't-care
        lstm_layer<KT2>(sbase, g_W2p, c2, hnew, wm, wn, lane);
        __syncthreads();
        store_h(smem, hnew, 272, wm, wn, lane);                 // h2 -> cols 272..527
        __syncthreads();
    }

    // dense + log-softmax loss
    float* logits = (float*)(smem + SM_LOGITS);
    for (int item = tid; item < M_CTA * NCLS; item += NTHREADS) {
        int row = item / NCLS, cls = item - row * NCLS;
        const __nv_bfloat16* h2p = (const __nv_bfloat16*)(smem + row * A_STRIDE_B + 272 * 2);
        float acc = __ldg(&bd[cls]);
#pragma unroll 8
        for (int k = 0; k < HID; k++)
            acc += __bfloat162float(h2p[k]) * __ldg(&Wd[k * NCLS + cls]);
        logits[item] = acc;
    }
    __syncthreads();
    if (tid < M_CTA) {
        const float* lr = logits + tid * NCLS;
        float mx = -1e30f;
        for (int c = 0; c < NCLS; c++) mx = fmaxf(mx, lr[c]);
        float s = 0.f;
        for (int c = 0; c < NCLS; c++) s += __expf(lr[c] - mx);
        int lab = labels[rowbase + tid];
        out[rowbase + tid] = mx + __logf(s) - lr[lab];
    }
}

extern "C" void kernel_launch(void* const* d_in, const int* in_sizes, int n_in,
                              void* d_out, int out_size)
{
    const int*   features  = (const int*)  d_in[0];
    const int*   labels    = (const int*)  d_in[1];
    const float* embedding = (const float*)d_in[2];
    const float* W1        = (const float*)d_in[3];
    const float* b1        = (const float*)d_in[4];
    const float* W2        = (const float*)d_in[5];
    const float* b2        = (const float*)d_in[6];
    const float* Wd        = (const float*)d_in[7];
    const float* bd        = (const float*)d_in[8];
    float* out = (float*)d_out;

    int ntot = N1PK + N2PK;
    pack_all<<<(ntot + 255) / 256, 256>>>(W1, b1, W2, b2);

    cudaFuncSetAttribute(lstm_kernel, cudaFuncAttributeMaxDynamicSharedMemorySize, SM_TOTAL);
    lstm_kernel<<<NCTA, NTHREADS, SM_TOTAL>>>(features, labels, embedding, Wd, bd, out);
}

// round 13
// speedup vs baseline: 1.8051x; 1.8051x over previous
#include <cuda_runtime.h>
#include <cuda_bf16.h>
#include <cstdint>

#define T_SEQ   80
#define NCLS    80
#define HID     256
#define EMB     8
#define BATCH   8192
#define GATES   1024
#define M_CTA   64
#define NCTA    (BATCH / M_CTA)
#define NTHREADS 512

#define KT1     18                  // layer1 K = 288 (bias+pad+x+h1+zero-pad), even
#define KT2     33                  // layer2 K = 528 (odd -> one peeled tail k-tile)
#define A_STRIDE   536              // bf16 elems/row; 1072B % 128 = 48 -> conflict-free ldmatrix
#define A_STRIDE_B (A_STRIDE * 2)
#define C_STRIDE   264

#define SM_A        0
#define SM_A_BYTES  (M_CTA * A_STRIDE_B)
#define SM_C1       SM_A_BYTES
#define SM_CBYTES   (M_CTA * C_STRIDE * 4)
#define SM_C2       (SM_C1 + SM_CBYTES)
#define SM_EMB      (SM_C2 + SM_CBYTES)
#define SM_LOGITS   (SM_EMB + NCLS * EMB * 4)
#define SM_TOTAL    (SM_LOGITS + M_CTA * NCLS * 4)   // 226816 bytes

// Packed weights, hidden-16-block major (as R12):
//   uint2 flat = ((hp*KT + kt)*32 + lane)*8 + (gi*2 + nh),  hp in [0,16)
//   n = gi*256 + hp*16 + nh*8 + (lane>>2); k rows k0,k0+1,k0+8,k0+9, k0=kt*16+(lane&3)*2
// Per (kt,lane): 4 contiguous uint4 -> 4x LDG.128 per k-tile covering N=64.
#define N1PK (32 * KT1 * 128)
#define N2PK (32 * KT2 * 128)
__device__ uint4 g_W1p[32 * KT1 * 64];
__device__ uint4 g_W2p[32 * KT2 * 64];

// Extended row r: r==0 -> bias[n]; r<woff or r>=rmax -> 0; else W[r-woff][n]
__global__ void pack_all(const float* __restrict__ W1, const float* __restrict__ b1,
                         const float* __restrict__ W2, const float* __restrict__ b2)
{
    int idx = blockIdx.x * blockDim.x + threadIdx.x;
    if (idx >= N1PK + N2PK) return;
    const float *W, *b; uint2* out; int KT, woff, rmax, rem;
    if (idx < N1PK) { W = W1; b = b1; out = (uint2*)g_W1p; KT = KT1; woff = 8;  rmax = 272; rem = idx; }
    else            { W = W2; b = b2; out = (uint2*)g_W2p; KT = KT2; woff = 16; rmax = 528; rem = idx - N1PK; }
    int frag = rem & 7;                  // gi*2 + nh
    int gi   = frag >> 1;
    int nh   = frag & 1;
    int lane = (rem >> 3) & 31;
    int t    = rem >> 8;
    int kt   = t % KT;
    int hp   = t / KT;
    int th = lane & 3, g = lane >> 2;
    int n  = gi * 256 + hp * 16 + nh * 8 + g;
    int k0 = kt * 16 + th * 2;
    float v[4];
#pragma unroll
    for (int i = 0; i < 4; i++) {
        int r = k0 + ((i >> 1) * 8) + (i & 1);
        float val;
        if (r == 0)                     val = b[n];
        else if (r < woff || r >= rmax) val = 0.f;
        else                            val = W[(size_t)(r - woff) * GATES + n];
        v[i] = val;
    }
    __nv_bfloat162 p0 = __floats2bfloat162_rn(v[0], v[1]);
    __nv_bfloat162 p1 = __floats2bfloat162_rn(v[2], v[3]);
    uint2 o;
    o.x = *reinterpret_cast<uint32_t*>(&p0);
    o.y = *reinterpret_cast<uint32_t*>(&p1);
    out[rem] = o;
}

__device__ __forceinline__ float fast_tanh(float x) {
    float y; asm("tanh.approx.f32 %0, %1;" : "=f"(y) : "f"(x)); return y;
}
__device__ __forceinline__ float fast_sigmoid(float x) {
    return fmaf(fast_tanh(0.5f * x), 0.5f, 0.5f);
}
__device__ __forceinline__ void ldsm4(uint32_t a[4], uint32_t addr) {
    asm volatile("ldmatrix.sync.aligned.m8n8.x4.shared.b16 {%0,%1,%2,%3}, [%4];\n"
                 : "=r"(a[0]), "=r"(a[1]), "=r"(a[2]), "=r"(a[3]) : "r"(addr));
}
__device__ __forceinline__ void mma_bf16(float c[4], const uint32_t a[4], uint32_t b0, uint32_t b1) {
    asm volatile("mma.sync.aligned.m16n8k16.row.col.f32.bf16.bf16.f32 "
                 "{%0,%1,%2,%3}, {%4,%5,%6,%7}, {%8,%9}, {%0,%1,%2,%3};\n"
                 : "+f"(c[0]), "+f"(c[1]), "+f"(c[2]), "+f"(c[3])
                 : "r"(a[0]), "r"(a[1]), "r"(a[2]), "r"(a[3]), "r"(b0), "r"(b1));
}

// 16 mmas of one k-tile: M=32 (2 mt frags) x N=64 (4 gates x 2 n8-halves).
__device__ __forceinline__ void do16(float (&acc)[2][4][2][4], const uint32_t (&af)[2][4],
                                     const uint4 (&S)[4])
{
#pragma unroll
    for (int mt = 0; mt < 2; mt++)
#pragma unroll
        for (int gi = 0; gi < 4; gi++) {
            mma_bf16(acc[mt][gi][0], af[mt], S[gi].x, S[gi].y);
            mma_bf16(acc[mt][gi][1], af[mt], S[gi].z, S[gi].w);
        }
}

// One LSTM layer. 16 warps = 2 wm (32 rows) x 8 wn. Each warp: 2 passes,
// pass p covers hidden cols [(wn*2+p)*16, +16) x 4 gates (N=64).
// B: 2-set prefetch in unroll-by-2 loop; odd KT handled by peeled tail.
template<int KT>
__device__ __forceinline__ void lstm_layer(
    uint32_t sbase, const uint4* __restrict__ Wp,
    float* __restrict__ cbuf, uint32_t (&hnew)[2][2][2][2],
    int wm, int wn, int lane)
{
    const int th = lane & 3, g = lane >> 2;
    const uint32_t a_base = sbase +
        (uint32_t)((wm * 32 + (lane & 15)) * A_STRIDE_B + ((lane >> 4) << 4));

#pragma unroll
    for (int p = 0; p < 2; p++) {
        const int hp = wn * 2 + p;
        float acc[2][4][2][4];
#pragma unroll
        for (int mt = 0; mt < 2; mt++)
#pragma unroll
            for (int gi = 0; gi < 4; gi++)
#pragma unroll
                for (int nh = 0; nh < 2; nh++)
#pragma unroll
                    for (int i = 0; i < 4; i++) acc[mt][gi][nh][i] = 0.f;

        const uint4* bb = Wp + ((size_t)(hp * KT) * 32 + lane) * 4;
        uint4 S0[4], S1[4];
#pragma unroll
        for (int j = 0; j < 4; j++) { S0[j] = __ldg(bb + j); S1[j] = __ldg(bb + 128 + j); }

        uint32_t af[2][4];
        uint32_t am = a_base;
        int kt = 0;
#pragma unroll 1
        for (; kt + 1 < KT; kt += 2) {
            // substep 0: consume S0(kt), refill S0 for kt+2
            ldsm4(af[0], am); ldsm4(af[1], am + 16 * A_STRIDE_B);
            do16(acc, af, S0);
            if (kt + 2 < KT) {
#pragma unroll
                for (int j = 0; j < 4; j++) S0[j] = __ldg(bb + 256 + j);
            }
            // substep 1: consume S1(kt+1), refill S1 for kt+3
            ldsm4(af[0], am + 32); ldsm4(af[1], am + 16 * A_STRIDE_B + 32);
            do16(acc, af, S1);
            if (kt + 3 < KT) {
#pragma unroll
                for (int j = 0; j < 4; j++) S1[j] = __ldg(bb + 384 + j);
            }
            bb += 256; am += 64;
        }
        if (kt < KT) {   // odd tail: S0 was prefetched for this kt by the last iteration
            ldsm4(af[0], am); ldsm4(af[1], am + 16 * A_STRIDE_B);
            do16(acc, af, S0);
        }

        // elementwise (i=0, j=1, f=2, o=3); thread owns rows wm*32+mt*16+g+rb*8,
        // cols hp*16 + nh*8 + th*2 (+q)
#pragma unroll
        for (int mt = 0; mt < 2; mt++)
#pragma unroll
            for (int nh = 0; nh < 2; nh++)
#pragma unroll
                for (int rb = 0; rb < 2; rb++) {
                    const int r = wm * 32 + mt * 16 + g + rb * 8;
                    float* cc = cbuf + r * C_STRIDE + hp * 16 + nh * 8 + th * 2;
                    float2 cold = *reinterpret_cast<float2*>(cc);
                    float co[2] = { cold.x, cold.y };
                    float nc[2], hv[2];
#pragma unroll
                    for (int q = 0; q < 2; q++) {
                        const int ci = rb * 2 + q;
                        nc[q] = co[q] * fast_sigmoid(acc[mt][2][nh][ci] + 1.0f)
                              + fast_sigmoid(acc[mt][0][nh][ci]) * fast_tanh(acc[mt][1][nh][ci]);
                        hv[q] = fast_tanh(nc[q]) * fast_sigmoid(acc[mt][3][nh][ci]);
                    }
                    *reinterpret_cast<float2*>(cc) = make_float2(nc[0], nc[1]);
                    __nv_bfloat162 hb = __floats2bfloat162_rn(hv[0], hv[1]);
                    hnew[p][mt][nh][rb] = *reinterpret_cast<uint32_t*>(&hb);
                }
    }
}

__device__ __forceinline__ void store_h(char* smem, const uint32_t (&hnew)[2][2][2][2],
                                        int hoff, int wm, int wn, int lane)
{
    const int th = lane & 3, g = lane >> 2;
#pragma unroll
    for (int p = 0; p < 2; p++) {
        const int hp = wn * 2 + p;
#pragma unroll
        for (int mt = 0; mt < 2; mt++)
#pragma unroll
            for (int nh = 0; nh < 2; nh++)
#pragma unroll
                for (int rb = 0; rb < 2; rb++) {
                    const int r = wm * 32 + mt * 16 + g + rb * 8;
                    const int col = hoff + hp * 16 + nh * 8 + th * 2;
                    *reinterpret_cast<uint32_t*>(smem + r * A_STRIDE_B + col * 2) =
                        hnew[p][mt][nh][rb];
                }
    }
}

__device__ __forceinline__ void write_x(char* smem, float* embs,
                                        const int* __restrict__ features,
                                        int rowbase, int t, int tid)
{
    if (tid < M_CTA) {
        int f = features[(rowbase + tid) * T_SEQ + t];
        const float* e = embs + f * EMB;
        uint32_t* dst = reinterpret_cast<uint32_t*>(smem + tid * A_STRIDE_B + 16);
#pragma unroll
        for (int i = 0; i < 4; i++) {
            __nv_bfloat162 p = __floats2bfloat162_rn(e[2 * i], e[2 * i + 1]);
            dst[i] = *reinterpret_cast<uint32_t*>(&p);
        }
    }
}

__global__ void __launch_bounds__(NTHREADS, 1) lstm_kernel(
    const int* __restrict__ features, const int* __restrict__ labels,
    const float* __restrict__ embedding,
    const float* __restrict__ Wd, const float* __restrict__ bd,
    float* __restrict__ out)
{
    extern __shared__ char smem[];
    const int tid = threadIdx.x;
    const int w = tid >> 5, lane = tid & 31;
    const int wm = w >> 3, wn = w & 7;
    const int rowbase = blockIdx.x * M_CTA;

    float* c1   = (float*)(smem + SM_C1);
    float* c2   = (float*)(smem + SM_C2);
    float* embs = (float*)(smem + SM_EMB);

    for (int i = tid; i < SM_TOTAL / 4; i += NTHREADS)
        ((uint32_t*)smem)[i] = 0u;
    __syncthreads();
    if (tid < M_CTA)
        *reinterpret_cast<__nv_bfloat16*>(smem + tid * A_STRIDE_B) = __float2bfloat16(1.0f);
    for (int i = tid; i < NCLS * EMB; i += NTHREADS) embs[i] = embedding[i];
    __syncthreads();
    write_x(smem, embs, features, rowbase, 0, tid);
    __syncthreads();

    const uint32_t sbase = (uint32_t)__cvta_generic_to_shared(smem);
    uint32_t hnew[2][2][2][2];

    for (int t = 0; t < T_SEQ; t++) {
        lstm_layer<KT1>(sbase, g_W1p, c1, hnew, wm, wn, lane);
        __syncthreads();
        store_h(smem, hnew, 16, wm, wn, lane);                  // h1 -> cols 16..271
        if (t + 1 < T_SEQ) write_x(smem, embs, features, rowbase, t + 1, tid);
        __syncthreads();   // layer2 reads x-cols against ZERO weight rows: values don't-care
        lstm_layer<KT2>(sbase, g_W2p, c2, hnew, wm, wn, lane);
        __syncthreads();
        store_h(smem, hnew, 272, wm, wn, lane);                 // h2 -> cols 272..527
        __syncthreads();
    }

    // dense + log-softmax loss
    float* logits = (float*)(smem + SM_LOGITS);
    for (int item = tid; item < M_CTA * NCLS; item += NTHREADS) {
        int row = item / NCLS, cls = item - row * NCLS;
        const __nv_bfloat16* h2p = (const __nv_bfloat16*)(smem + row * A_STRIDE_B + 272 * 2);
        float acc = __ldg(&bd[cls]);
#pragma unroll 8
        for (int k = 0; k < HID; k++)
            acc += __bfloat162float(h2p[k]) * __ldg(&Wd[k * NCLS + cls]);
        logits[item] = acc;
    }
    __syncthreads();
    if (tid < M_CTA) {
        const float* lr = logits + tid * NCLS;
        float mx = -1e30f;
        for (int c = 0; c < NCLS; c++) mx = fmaxf(mx, lr[c]);
        float s = 0.f;
        for (int c = 0; c < NCLS; c++) s += __expf(lr[c] - mx);
        int lab = labels[rowbase + tid];
        out[rowbase + tid] = mx + __logf(s) - lr[lab];
    }
}

extern "C" void kernel_launch(void* const* d_in, const int* in_sizes, int n_in,
                              void* d_out, int out_size)
{
    const int*   features  = (const int*)  d_in[0];
    const int*   labels    = (const int*)  d_in[1];
    const float* embedding = (const float*)d_in[2];
    const float* W1        = (const float*)d_in[3];
    const float* b1        = (const float*)d_in[4];
    const float* W2        = (const float*)d_in[5];
    const float* b2        = (const float*)d_in[6];
    const float* Wd        = (const float*)d_in[7];
    const float* bd        = (const float*)d_in[8];
    float* out = (float*)d_out;

    int ntot = N1PK + N2PK;
    pack_all<<<(ntot + 255) / 256, 256>>>(W1, b1, W2, b2);

    cudaFuncSetAttribute(lstm_kernel, cudaFuncAttributeMaxDynamicSharedMemorySize, SM_TOTAL);
    lstm_kernel<<<NCTA, NTHREADS, SM_TOTAL>>>(features, labels, embedding, Wd, bd, out);
}

// round 15
// speedup vs baseline: 3.4270x; 1.8985x over previous
#include <cuda_runtime.h>
#include <cuda_bf16.h>
#include <cstdint>

#define T_SEQ   80
#define NCLS    80
#define HID     256
#define EMB     8
#define BATCH   8192
#define GATES   1024
#define M_CTA   64
#define NCTA    (BATCH / M_CTA)
#define NTHREADS 512

#define KT1     18                  // layer1 K = 288 (bias+pad+x+h1+zero-pad), %3==0
#define KT2     33                  // layer2 K = 528, %3==0
#define A_STRIDE   536              // bf16 elems/row; 1072B % 128 = 48 -> conflict-free ldmatrix
#define A_STRIDE_B (A_STRIDE * 2)
#define C_STRIDE   264

#define SM_A        0
#define SM_A_BYTES  (M_CTA * A_STRIDE_B)
#define SM_C1       SM_A_BYTES
#define SM_CBYTES   (M_CTA * C_STRIDE * 4)
#define SM_C2       (SM_C1 + SM_CBYTES)
#define SM_EMB      (SM_C2 + SM_CBYTES)
#define SM_LOGITS   (SM_EMB + NCLS * EMB * 4)        // logits scratch doubles as h-stage
#define SM_TOTAL    (SM_LOGITS + M_CTA * NCLS * 4)   // 226816 bytes
#define HSTAGE_STRIDE 272                             // 64*272=17408 <= 20480; 16B-aligned rows

// Packed weights, gate-interleaved fragment-major (PROVEN R10 format):
//   uint2 index = ((nt*KT + kt)*32 + lane)*4 + gi,  nt = hidden-8-block in [0,32), gi in [0,4)
// Column n = gi*256 + nt*8 + (lane>>2); rows k0,k0+1,k0+8,k0+9, k0 = kt*16+(lane&3)*2.
#define N1PK (32 * KT1 * 128)
#define N2PK (32 * KT2 * 128)
__device__ uint4 g_W1p[32 * KT1 * 64];
__device__ uint4 g_W2p[32 * KT2 * 64];

// Extended row r: r==0 -> bias[n]; r<woff or r>=rmax -> 0; else W[r-woff][n]
__global__ void pack_all(const float* __restrict__ W1, const float* __restrict__ b1,
                         const float* __restrict__ W2, const float* __restrict__ b2)
{
    int idx = blockIdx.x * blockDim.x + threadIdx.x;
    if (idx >= N1PK + N2PK) return;
    const float *W, *b; uint2* out; int KT, woff, rmax, rem;
    if (idx < N1PK) { W = W1; b = b1; out = (uint2*)g_W1p; KT = KT1; woff = 8;  rmax = 272; rem = idx; }
    else            { W = W2; b = b2; out = (uint2*)g_W2p; KT = KT2; woff = 16; rmax = 528; rem = idx - N1PK; }
    int gi   = rem & 3;
    int lane = (rem >> 2) & 31;
    int t    = rem >> 7;
    int kt   = t % KT;
    int nt   = t / KT;
    int th = lane & 3, g = lane >> 2;
    int n  = gi * 256 + nt * 8 + g;
    int k0 = kt * 16 + th * 2;
    float v[4];
#pragma unroll
    for (int i = 0; i < 4; i++) {
        int r = k0 + ((i >> 1) * 8) + (i & 1);
        float val;
        if (r == 0)                     val = b[n];
        else if (r < woff || r >= rmax) val = 0.f;
        else                            val = W[(size_t)(r - woff) * GATES + n];
        v[i] = val;
    }
    __nv_bfloat162 p0 = __floats2bfloat162_rn(v[0], v[1]);
    __nv_bfloat162 p1 = __floats2bfloat162_rn(v[2], v[3]);
    uint2 o;
    o.x = *reinterpret_cast<uint32_t*>(&p0);
    o.y = *reinterpret_cast<uint32_t*>(&p1);
    out[rem] = o;
}

__device__ __forceinline__ float fast_tanh(float x) {
    float y; asm("tanh.approx.f32 %0, %1;" : "=f"(y) : "f"(x)); return y;
}
__device__ __forceinline__ float fast_sigmoid(float x) {
    return fmaf(fast_tanh(0.5f * x), 0.5f, 0.5f);
}
__device__ __forceinline__ void ldsm4(uint32_t a[4], uint32_t addr) {
    asm volatile("ldmatrix.sync.aligned.m8n8.x4.shared.b16 {%0,%1,%2,%3}, [%4];\n"
                 : "=r"(a[0]), "=r"(a[1]), "=r"(a[2]), "=r"(a[3]) : "r"(addr));
}
__device__ __forceinline__ void mma_bf16(float c[4], const uint32_t a[4], uint32_t b0, uint32_t b1) {
    asm volatile("mma.sync.aligned.m16n8k16.row.col.f32.bf16.bf16.f32 "
                 "{%0,%1,%2,%3}, {%4,%5,%6,%7}, {%8,%9}, {%0,%1,%2,%3};\n"
                 : "+f"(c[0]), "+f"(c[1]), "+f"(c[2]), "+f"(c[3])
                 : "r"(a[0]), "r"(a[1]), "r"(a[2]), "r"(a[3]), "r"(b0), "r"(b1));
}

// One substep (one k-tile): 4 M-fragments x (4 gates), af ping-pong prefetch.
__device__ __forceinline__ void sub_mts(float (&acc)[4][4][4], uint32_t (&af)[2][4],
                                        const uint4& Sa, const uint4& Sb,
                                        uint32_t col_addr, uint32_t next_addr, bool pref_next)
{
#pragma unroll
    for (int mt = 0; mt < 4; mt++) {
        const int cur = mt & 1, nxt = cur ^ 1;
        if (mt < 3)
            ldsm4(af[nxt], col_addr + (uint32_t)((mt + 1) * (16 * A_STRIDE_B)));
        else if (pref_next)
            ldsm4(af[nxt], next_addr);
        mma_bf16(acc[mt][0], af[cur], Sa.x, Sa.y);
        mma_bf16(acc[mt][1], af[cur], Sa.z, Sa.w);
        mma_bf16(acc[mt][2], af[cur], Sb.x, Sb.y);
        mma_bf16(acc[mt][3], af[cur], Sb.z, Sb.w);
    }
}

// One LSTM layer for 64 rows. 16 warps, each warp: Mw=64 (full M), Nw=32
// (8 hidden cols x 4 gates), 2 waves (hblk = wave*16 + wn). Wave-0 h is staged
// in smem (logits region); wave-1 h returns in registers.
template<int KT>
__device__ __forceinline__ void lstm_layer(
    uint32_t sbase, const uint4* __restrict__ Wp,
    float* __restrict__ cbuf, char* __restrict__ hstage,
    uint32_t (&hnew)[4][2], int wn, int lane)
{
    static_assert(KT % 3 == 0, "KT must be divisible by 3");
    const int th = lane & 3, g = lane >> 2;
    const uint32_t a_base = sbase +
        (uint32_t)((lane & 15) * A_STRIDE_B + ((lane >> 4) << 4));

#pragma unroll
    for (int wave = 0; wave < 2; wave++) {
        const int hblk = wave * 16 + wn;
        float acc[4][4][4];
#pragma unroll
        for (int mt = 0; mt < 4; mt++)
#pragma unroll
            for (int gi = 0; gi < 4; gi++)
#pragma unroll
                for (int i = 0; i < 4; i++) acc[mt][gi][i] = 0.f;

        const uint4* bb = Wp + ((size_t)(hblk * KT) * 32 + lane) * 2;
        uint4 A0 = __ldg(bb + 0),   A1 = __ldg(bb + 1);     // kt+0
        uint4 B0 = __ldg(bb + 64),  B1 = __ldg(bb + 65);    // kt+1
        uint4 C0 = __ldg(bb + 128), C1 = __ldg(bb + 129);   // kt+2

        uint32_t af[2][4];
        uint32_t am = a_base;
        ldsm4(af[0], am);                                   // (kt0, mt0)

#pragma unroll 1
        for (int kt = 0; kt < KT; kt += 3) {
            sub_mts(acc, af, A0, A1, am, am + 32, true);
            if (kt + 3 < KT) { A0 = __ldg(bb + 192); A1 = __ldg(bb + 193); }
            sub_mts(acc, af, B0, B1, am + 32, am + 64, true);
            if (kt + 4 < KT) { B0 = __ldg(bb + 256); B1 = __ldg(bb + 257); }
            sub_mts(acc, af, C0, C1, am + 64, am + 96, kt + 3 < KT);
            if (kt + 5 < KT) { C0 = __ldg(bb + 320); C1 = __ldg(bb + 321); }
            bb += 192; am += 96;
        }

        // elementwise (i=0, j=1, f=2, o=3); thread rows mt*16+g+rb*8,
        // hidden cols hblk*8 + th*2 (+q)
        const int col = hblk * 8 + th * 2;
#pragma unroll
        for (int mt = 0; mt < 4; mt++)
#pragma unroll
            for (int rb = 0; rb < 2; rb++) {
                const int r = mt * 16 + g + rb * 8;
                float* cc = cbuf + r * C_STRIDE + col;
                float2 cold = *reinterpret_cast<float2*>(cc);
                float co[2] = { cold.x, cold.y };
                float nc[2], hv[2];
#pragma unroll
                for (int q = 0; q < 2; q++) {
                    const int ci = rb * 2 + q;
                    nc[q] = co[q] * fast_sigmoid(acc[mt][2][ci] + 1.0f)
                          + fast_sigmoid(acc[mt][0][ci]) * fast_tanh(acc[mt][1][ci]);
                    hv[q] = fast_tanh(nc[q]) * fast_sigmoid(acc[mt][3][ci]);
                }
                *reinterpret_cast<float2*>(cc) = make_float2(nc[0], nc[1]);
                __nv_bfloat162 hb = __floats2bfloat162_rn(hv[0], hv[1]);
                uint32_t packed = *reinterpret_cast<uint32_t*>(&hb);
                if (wave == 0)
                    *reinterpret_cast<uint32_t*>(hstage + r * HSTAGE_STRIDE + col * 2) = packed;
                else
                    hnew[mt][rb] = packed;
            }
    }
}

// Commit new h into the A tile: wave-1 from registers, wave-0 via staged copy.
__device__ __forceinline__ void commit_h(char* smem, const char* hstage,
                                         const uint32_t (&hnew)[4][2],
                                         int hoff, int wn, int lane, int tid)
{
    const int th = lane & 3, g = lane >> 2;
    const int col = (16 + wn) * 8 + th * 2;          // wave-1 cols 128..255
#pragma unroll
    for (int mt = 0; mt < 4; mt++)
#pragma unroll
        for (int rb = 0; rb < 2; rb++) {
            const int r = mt * 16 + g + rb * 8;
            *reinterpret_cast<uint32_t*>(smem + r * A_STRIDE_B + (hoff + col) * 2) = hnew[mt][rb];
        }
    // wave-0: copy 64 rows x 256B (hidden cols 0..127) from hstage into A
#pragma unroll
    for (int it = 0; it < 2; it++) {
        int idx = tid + it * NTHREADS;               // 0..1023
        int row = idx >> 4, seg = idx & 15;
        uint4 v = *reinterpret_cast<const uint4*>(hstage + row * HSTAGE_STRIDE + seg * 16);
        *reinterpret_cast<uint4*>(smem + row * A_STRIDE_B + hoff * 2 + seg * 16) = v;
    }
}

__device__ __forceinline__ void write_x(char* smem, float* embs,
                                        const int* __restrict__ features,
                                        int rowbase, int t, int tid)
{
    if (tid < M_CTA) {
        int f = features[(rowbase + tid) * T_SEQ + t];
        const float* e = embs + f * EMB;
        uint32_t* dst = reinterpret_cast<uint32_t*>(smem + tid * A_STRIDE_B + 16);
#pragma unroll
        for (int i = 0; i < 4; i++) {
            __nv_bfloat162 p = __floats2bfloat162_rn(e[2 * i], e[2 * i + 1]);
            dst[i] = *reinterpret_cast<uint32_t*>(&p);
        }
    }
}

__global__ void __launch_bounds__(NTHREADS, 1) lstm_kernel(
    const int* __restrict__ features, const int* __restrict__ labels,
    const float* __restrict__ embedding,
    const float* __restrict__ Wd, const float* __restrict__ bd,
    float* __restrict__ out)
{
    extern __shared__ char smem[];
    const int tid = threadIdx.x;
    const int wn = tid >> 5, lane = tid & 31;
    const int rowbase = blockIdx.x * M_CTA;

    float* c1     = (float*)(smem + SM_C1);
    float* c2     = (float*)(smem + SM_C2);
    float* embs   = (float*)(smem + SM_EMB);
    char*  hstage = smem + SM_LOGITS;                // shared with logits scratch (disjoint in time)

    for (int i = tid; i < SM_TOTAL / 4; i += NTHREADS)
        ((uint32_t*)smem)[i] = 0u;
    __syncthreads();
    if (tid < M_CTA)
        *reinterpret_cast<__nv_bfloat16*>(smem + tid * A_STRIDE_B) = __float2bfloat16(1.0f);
    for (int i = tid; i < NCLS * EMB; i += NTHREADS) embs[i] = embedding[i];
    __syncthreads();
    write_x(smem, embs, features, rowbase, 0, tid);
    __syncthreads();

    const uint32_t sbase = (uint32_t)__cvta_generic_to_shared(smem);
    uint32_t hnew[4][2];

    for (int t = 0; t < T_SEQ; t++) {
        lstm_layer<KT1>(sbase, g_W1p, c1, hstage, hnew, wn, lane);
        __syncthreads();                 // all A reads + hstage writes done
        commit_h(smem, hstage, hnew, 16, wn, lane, tid);     // h1 -> cols 16..271
        if (t + 1 < T_SEQ) write_x(smem, embs, features, rowbase, t + 1, tid);
        __syncthreads();   // layer2 reads x-cols against ZERO weight rows: values don't-care
        lstm_layer<KT2>(sbase, g_W2p, c2, hstage, hnew, wn, lane);
        __syncthreads();
        commit_h(smem, hstage, hnew, 272, wn, lane, tid);    // h2 -> cols 272..527
        __syncthreads();
    }

    // dense + log-softmax loss (logits region free again)
    float* logits = (float*)(smem + SM_LOGITS);
    for (int item = tid; item < M_CTA * NCLS; item += NTHREADS) {
        int row = item / NCLS, cls = item - row * NCLS;
        const __nv_bfloat16* h2p = (const __nv_bfloat16*)(smem + row * A_STRIDE_B + 272 * 2);
        float acc = __ldg(&bd[cls]);
#pragma unroll 8
        for (int k = 0; k < HID; k++)
            acc += __bfloat162float(h2p[k]) * __ldg(&Wd[k * NCLS + cls]);
        logits[item] = acc;
    }
    __syncthreads();
    if (tid < M_CTA) {
        const float* lr = logits + tid * NCLS;
        float mx = -1e30f;
        for (int c = 0; c < NCLS; c++) mx = fmaxf(mx, lr[c]);
        float s = 0.f;
        for (int c = 0; c < NCLS; c++) s += __expf(lr[c] - mx);
        int lab = labels[rowbase + tid];
        out[rowbase + tid] = mx + __logf(s) - lr[lab];
    }
}

extern "C" void kernel_launch(void* const* d_in, const int* in_sizes, int n_in,
                              void* d_out, int out_size)
{
    const int*   features  = (const int*)  d_in[0];
    const int*   labels    = (const int*)  d_in[1];
    const float* embedding = (const float*)d_in[2];
    const float* W1        = (const float*)d_in[3];
    const float* b1        = (const float*)d_in[4];
    const float* W2        = (const float*)d_in[5];
    const float* b2        = (const float*)d_in[6];
    const float* Wd        = (const float*)d_in[7];
    const float* bd        = (const float*)d_in[8];
    float* out = (float*)d_out;

    int ntot = N1PK + N2PK;
    pack_all<<<(ntot + 255) / 256, 256>>>(W1, b1, W2, b2);

    cudaFuncSetAttribute(lstm_kernel, cudaFuncAttributeMaxDynamicSharedMemorySize, SM_TOTAL);
    lstm_kernel<<<NCTA, NTHREADS, SM_TOTAL>>>(features, labels, embedding, Wd, bd, out);
}